// round 1
// baseline (speedup 1.0000x reference)
#include <cuda_runtime.h>
#include <cuda_bf16.h>

// FeatureVectorInteractions: out[b] = < sum_i m0_i V0[b,i,:], sum_j m1_j V1[b,j,:] >
// B=4096, N=128, D=64. Inputs (metadata order): VI0 int32[B,N], VI1 int32[B,N],
// V0 f32[B,N,D], V1 f32[B,N,D]. Output f32[B,1].
//
// HBM-bound: 268 MB of V reads. One CTA per batch row; float4-vectorized,
// fully coalesced, MLP=16 per thread.

#define NB 128   // N
#define DV 64    // D
#define F4_PER_ROW (DV / 4)          // 16 float4 per row
#define F4_PER_BATCH (NB * F4_PER_ROW) // 2048

__global__ __launch_bounds__(256, 8)
void fvi_kernel(const int* __restrict__ VI0,
                const int* __restrict__ VI1,
                const float4* __restrict__ V0,
                const float4* __restrict__ V1,
                float* __restrict__ out)
{
    const int b   = blockIdx.x;
    const int tid = threadIdx.x;
    const int r   = tid >> 4;   // 0..15 : row-group
    const int c   = tid & 15;   // 0..15 : float4 column (d/4)

    __shared__ float m0s[NB];
    __shared__ float m1s[NB];
    __shared__ float4 red0[16][16];
    __shared__ float4 red1[16][16];

    // masks: clip(VI,0,1) on int -> (VI > 0) ? 1 : 0
    if (tid < NB) {
        m0s[tid] = (VI0[b * NB + tid] > 0) ? 1.0f : 0.0f;
    } else {
        const int i = tid - NB;
        m1s[i] = (VI1[b * NB + i] > 0) ? 1.0f : 0.0f;
    }
    __syncthreads();

    const float4* v0 = V0 + (size_t)b * F4_PER_BATCH;
    const float4* v1 = V1 + (size_t)b * F4_PER_BATCH;

    float4 a0 = make_float4(0.f, 0.f, 0.f, 0.f);
    float4 a1 = make_float4(0.f, 0.f, 0.f, 0.f);

    #pragma unroll
    for (int k = 0; k < 8; k++) {
        const int i = r + k * 16;          // row index 0..127
        const float m0 = m0s[i];
        const float m1 = m1s[i];
        const float4 x = v0[i * F4_PER_ROW + c];
        const float4 y = v1[i * F4_PER_ROW + c];
        a0.x = fmaf(m0, x.x, a0.x);
        a0.y = fmaf(m0, x.y, a0.y);
        a0.z = fmaf(m0, x.z, a0.z);
        a0.w = fmaf(m0, x.w, a0.w);
        a1.x = fmaf(m1, y.x, a1.x);
        a1.y = fmaf(m1, y.y, a1.y);
        a1.z = fmaf(m1, y.z, a1.z);
        a1.w = fmaf(m1, y.w, a1.w);
    }

    red0[r][c] = a0;
    red1[r][c] = a1;
    __syncthreads();

    // tree-reduce over r: 16 -> 1
    #pragma unroll
    for (int s = 8; s > 0; s >>= 1) {
        if (r < s) {
            float4 p = red0[r + s][c];
            a0.x += p.x; a0.y += p.y; a0.z += p.z; a0.w += p.w;
            red0[r][c] = a0;
            float4 q = red1[r + s][c];
            a1.x += q.x; a1.y += q.y; a1.z += q.z; a1.w += q.w;
            red1[r][c] = a1;
        }
        __syncthreads();
    }

    // final dot: lanes 0..15 each handle one float4 column, shuffle-reduce
    if (tid < 32) {
        float val = 0.0f;
        if (tid < 16) {
            const float4 u0 = red0[0][tid];
            const float4 u1 = red1[0][tid];
            val = u0.x * u1.x + u0.y * u1.y + u0.z * u1.z + u0.w * u1.w;
        }
        #pragma unroll
        for (int o = 8; o > 0; o >>= 1)
            val += __shfl_xor_sync(0xffffffffu, val, o);
        if (tid == 0) out[b] = val;
    }
}

extern "C" void kernel_launch(void* const* d_in, const int* in_sizes, int n_in,
                              void* d_out, int out_size)
{
    const int*    VI0 = (const int*)d_in[0];
    const int*    VI1 = (const int*)d_in[1];
    const float4* V0  = (const float4*)d_in[2];
    const float4* V1  = (const float4*)d_in[3];
    float*        out = (float*)d_out;

    const int B = in_sizes[0] / NB;   // 4096
    fvi_kernel<<<B, 256>>>(VI0, VI1, V0, V1, out);
}